// round 6
// baseline (speedup 1.0000x reference)
#include <cuda_runtime.h>
#include <cuda_fp16.h>
#include <math.h>

#define Nn   262144
#define Ee   2097152
#define Bn   16
#define GXn  22
#define Gn   484
#define Sn   7744
#define EPSn 1e-5f
#define SXn  (16.0f/346.0f)
#define SYn  (12.0f/260.0f)
#define NCPY 64
#define MARKW ((Bn*Gn*Gn + 31)/32)

// ---------------- scratch (device globals; no allocations) ----------------
__device__ int      d_deg [Nn];
__device__ int      d_rs  [Nn+1];
__device__ int      d_cur [Nn+1];
__device__ uint2    d_eP  [Ee];      // packed: src(18b)+b2(14b) | b0(16b)+b1(16b)
__device__ int      d_bsums[256];
__device__ int      d_cid [Nn];
__device__ int      d_ccnt[Sn];
__device__ float    d_pp  [Sn*2];
__device__ unsigned d_xpe [Sn*32];
__device__ __half   d_xph [Sn*32];
__device__ float    d_wv  [Sn];
__device__ unsigned d_markb[MARKW];
__device__ int      d_EcD [1];
__device__ int      d_csrc[Ee];
__device__ int      d_cdst[Ee];
__device__ int      d_degc[Sn];
__device__ int      d_rsc [Sn+1];
__device__ int      d_curc[Sn+1];
__device__ uint2    d_ePc [Ee];
__device__ unsigned d_mxD [1];
__device__ float    d_twD [1];
__device__ __half   d_H0 [(size_t)Nn*16];   // padded input x
__device__ __half   d_Ha [(size_t)Nn*32];
__device__ __half   d_Hb [(size_t)Nn*32];
__device__ __half   d_Hc [(size_t)Nn*32];
__device__ __half   d_Ch0[Sn*32];
__device__ __half   d_Ch1[Sn*32];
__device__ float    d_bnaccM[8][NCPY][128];
__device__ float    d_ssbL[8][64];

// ---------------- helpers ----------------
__device__ __forceinline__ unsigned encf(float f){
    unsigned u = __float_as_uint(f);
    return (u & 0x80000000u) ? ~u : (u | 0x80000000u);
}
__device__ __forceinline__ float decf(unsigned u){
    return (u & 0x80000000u) ? __uint_as_float(u & 0x7FFFFFFFu) : __uint_as_float(~u);
}
__device__ __forceinline__ uint2 pack_edge(int s, float b0, float b1, float b2){
    unsigned q0 = (unsigned)__float2int_rn(b0*65535.f);
    unsigned q1 = (unsigned)__float2int_rn(b1*65535.f);
    unsigned q2 = (unsigned)__float2int_rn(b2*16383.f);
    uint2 r;
    r.x = ((unsigned)s << 14) | q2;
    r.y = q0 | (q1 << 16);
    return r;
}
__device__ __forceinline__ void unpack_b(uint2 e, float& b0, float& b1, float& b2, float& b3){
    b2 = (float)(e.x & 0x3FFFu) * (1.f/16383.f);
    b0 = (float)(e.y & 0xFFFFu) * (1.f/65535.f);
    b1 = (float)(e.y >> 16)     * (1.f/65535.f);
    b3 = 1.f - b0 - b1 - b2;
}

// ---------------- prolog ----------------
__global__ void k_zeros(){
    int i = blockIdx.x*blockDim.x + threadIdx.x;
    int st = gridDim.x*blockDim.x;
    for (int j=i; j<MARKW;    j+=st) d_markb[j]=0u;
    for (int j=i; j<Nn;       j+=st) d_deg[j]=0;
    for (int j=i; j<Sn;       j+=st){ d_ccnt[j]=0; d_degc[j]=0; }
    for (int j=i; j<Sn*2;     j+=st) d_pp[j]=0.f;
    for (int j=i; j<Sn*32;    j+=st) d_xpe[j]=0u;
    float* bm = &d_bnaccM[0][0][0];
    for (int j=i; j<8*NCPY*128; j+=st) bm[j]=0.f;
    if (i==0){ d_EcD[0]=0; d_mxD[0]=0u; d_twD[0]=0.f; }
}

// fused: edge dst histogram + node cell assignment + x -> padded half
__global__ void k_prep(const int* __restrict__ dst, const float* __restrict__ pos,
                       const int* __restrict__ batch, const float* __restrict__ x){
    int e = blockIdx.x*blockDim.x + threadIdx.x;
    if (e < Ee) atomicAdd(&d_deg[dst[e]], 1);
    if (e < Nn){
        float px = pos[2*(size_t)e], py = pos[2*(size_t)e+1];
        int cx = min(max((int)floorf(px / SXn), 0), GXn-1);
        int cy = min(max((int)floorf(py / SYn), 0), GXn-1);
        int cid = batch[e]*Gn + cy*GXn + cx;
        d_cid[e] = cid;
        atomicAdd(&d_ccnt[cid], 1);
        atomicAdd(&d_pp[2*cid],   px);
        atomicAdd(&d_pp[2*cid+1], py);
        const float* xr = x + (size_t)e*10;
        __half* hr = d_H0 + (size_t)e*16;
        #pragma unroll
        for (int i=0;i<10;i++) hr[i] = __float2half(xr[i]);
        #pragma unroll
        for (int i=10;i<16;i++) hr[i] = __float2half(0.f);
    }
}

// ---------------- exclusive scan (3 kernels) ----------------
__global__ void k_scan1(const int* __restrict__ in, int* __restrict__ out, int n){
    __shared__ int sh[1024];
    int t = threadIdx.x;
    int base = blockIdx.x*1024;
    int v = (base+t < n) ? in[base+t] : 0;
    sh[t] = v; __syncthreads();
    for (int off=1; off<1024; off<<=1){
        int a = (t>=off) ? sh[t-off] : 0;
        __syncthreads();
        sh[t] += a;
        __syncthreads();
    }
    if (base+t < n) out[base+t] = sh[t]-v;
    if (t==1023) d_bsums[blockIdx.x] = sh[1023];
}
__global__ void k_scan2(int nb){
    __shared__ int sh[256];
    int t = threadIdx.x;
    int v = (t<nb) ? d_bsums[t] : 0;
    sh[t] = v; __syncthreads();
    for (int off=1; off<256; off<<=1){
        int a = (t>=off) ? sh[t-off] : 0;
        __syncthreads();
        sh[t] += a;
        __syncthreads();
    }
    if (t<nb) d_bsums[t] = sh[t]-v;
}
__global__ void k_scan3(const int* __restrict__ in, int* __restrict__ out, int* __restrict__ cur, int n){
    int i = blockIdx.x*blockDim.x + threadIdx.x;
    if (i >= n) return;
    int v = out[i] + d_bsums[i>>10];
    out[i] = v; cur[i] = v;
    if (i == n-1){ int tot = v + in[i]; out[n]=tot; cur[n]=tot; }
}

// scatter edges into CSR order as packed uint2
__global__ void k_scatter(const int* __restrict__ src, const int* __restrict__ dst,
                          const float* __restrict__ ea){
    int e = blockIdx.x*blockDim.x + threadIdx.x;
    if (e >= Ee) return;
    float f0 = fminf(fmaxf(ea[2*(size_t)e  ], 0.f), 1.f);
    float f1 = fminf(fmaxf(ea[2*(size_t)e+1], 0.f), 1.f);
    int p = atomicAdd(&d_cur[dst[e]], 1);
    d_eP[p] = pack_edge(src[e], (1.f-f0)*(1.f-f1), f0*(1.f-f1), (1.f-f0)*f1);
}

// ---------------- fused layer: aggregate -> GEMM -> ELU -> BN reduce ----------------
// A_k[d,i] = sum_e bas_k(e) * X[src_e, i];  s_k[d] = sum_e bas_k(e)
// in_k[i]  = a1_i*A1_k[i] + a2_i*A2_k[i] + (b1_i+b2_i)*s_k   (exact BN fold)
// v_c      = elu( (sum_k sum_i in_k[i]*W[k,i,c]) / max(deg,1) )
template<int CIN,int COUT>
__global__ void k_fuse(const __half* __restrict__ X1, const __half* __restrict__ X2,
                       const float* __restrict__ W, __half* __restrict__ uout,
                       const int* __restrict__ rs, const uint2* __restrict__ eP,
                       int layer, int wcin, int ab1, int ab2, int ndst){
    constexpr int MX = (CIN > COUT) ? CIN : COUT;
    constexpr int D  = 32/MX;            // dsts per warp
    __shared__ float Wsh[4*32*32];
    __shared__ float A1s[32], B1s[32], A2s[32];
    __shared__ float As[8][D][4][CIN];
    __shared__ float ss[8][33], sq[8][33];
    int tid = threadIdx.x;
    for (int idx = tid; idx < 4*wcin*COUT; idx += 256) Wsh[idx] = W[idx];
    if (tid < 32){
        A1s[tid] = (ab1 >= 0) ? d_ssbL[ab1][tid]    : 1.f;
        float b1 = (ab1 >= 0) ? d_ssbL[ab1][32+tid] : 0.f;
        A2s[tid] = (ab2 >= 0) ? d_ssbL[ab2][tid]    : 0.f;
        float b2 = (ab2 >= 0) ? d_ssbL[ab2][32+tid] : 0.f;
        B1s[tid] = b1 + b2;
    }
    __syncthreads();
    int w = tid >> 5, lane = tid & 31;
    int sub = lane / MX, il = lane % MX;
    int d = (blockIdx.x*8 + w)*D + sub;
    int beg = 0, end = 0;
    if (d < ndst){ beg = rs[d]; end = rs[d+1]; }
    float c0=0,c1=0,c2=0,c3=0;     // X1 basis-weighted sums
    float e0=0,e1=0,e2=0,e3=0;     // X2 basis-weighted sums
    float k0=0,k1=0,k2=0,k3=0;     // basis sums
    bool act = (il < CIN);
    int p = beg;
    for (; p + 1 < end; p += 2){
        uint2 ea = eP[p], eb = eP[p+1];
        int sa = (int)(ea.x >> 14), sb = (int)(eb.x >> 14);
        float xa=0, xb=0, ya=0, yb=0;
        if (act){
            xa = __half2float(X1[(size_t)sa*CIN + il]);
            xb = __half2float(X1[(size_t)sb*CIN + il]);
            if (X2){
                ya = __half2float(X2[(size_t)sa*CIN + il]);
                yb = __half2float(X2[(size_t)sb*CIN + il]);
            }
        }
        float p0,p1,p2,p3, q0,q1,q2,q3;
        unpack_b(ea, p0,p1,p2,p3);
        unpack_b(eb, q0,q1,q2,q3);
        c0 += p0*xa + q0*xb;  c1 += p1*xa + q1*xb;
        c2 += p2*xa + q2*xb;  c3 += p3*xa + q3*xb;
        k0 += p0 + q0;  k1 += p1 + q1;  k2 += p2 + q2;  k3 += p3 + q3;
        if (X2){
            e0 += p0*ya + q0*yb;  e1 += p1*ya + q1*yb;
            e2 += p2*ya + q2*yb;  e3 += p3*ya + q3*yb;
        }
    }
    if (p < end){
        uint2 ea = eP[p];
        int sa = (int)(ea.x >> 14);
        float xa=0, ya=0;
        if (act){
            xa = __half2float(X1[(size_t)sa*CIN + il]);
            if (X2) ya = __half2float(X2[(size_t)sa*CIN + il]);
        }
        float p0,p1,p2,p3;
        unpack_b(ea, p0,p1,p2,p3);
        c0 += p0*xa; c1 += p1*xa; c2 += p2*xa; c3 += p3*xa;
        k0 += p0; k1 += p1; k2 += p2; k3 += p3;
        if (X2){ e0 += p0*ya; e1 += p1*ya; e2 += p2*ya; e3 += p3*ya; }
    }
    if (act && d < ndst){
        float a1 = A1s[il], a2 = A2s[il], bb = B1s[il];
        As[w][sub][0][il] = a1*c0 + a2*e0 + bb*k0;
        As[w][sub][1][il] = a1*c1 + a2*e1 + bb*k1;
        As[w][sub][2][il] = a1*c2 + a2*e2 + bb*k2;
        As[w][sub][3][il] = a1*c3 + a2*e3 + bb*k3;
    }
    __syncwarp();
    float v = 0.f;
    bool outp = (d < ndst) && (il < COUT);
    if (outp){
        int c = il;
        #pragma unroll
        for (int k = 0; k < 4; k++){
            const float* wk = &Wsh[k*wcin*COUT];
            const float* ak = &As[w][sub][k][0];
            for (int i = 0; i < wcin; i++)
                v += ak[i] * wk[i*COUT + c];
        }
        int dg = end - beg; if (dg < 1) dg = 1;
        v /= (float)dg;
        v = (v > 0.f) ? v : expm1f(v);
        uout[(size_t)d*COUT + c] = __float2half(v);
    } else v = 0.f;
    ss[w][lane] = v; sq[w][lane] = v*v;
    __syncthreads();
    if (w == 0 && lane < COUT){
        float S = 0.f, Q = 0.f;
        #pragma unroll
        for (int j = 0; j < 8; j++){
            #pragma unroll
            for (int t = 0; t < D; t++){
                S += ss[j][t*MX + lane];
                Q += sq[j][t*MX + lane];
            }
        }
        int cp = blockIdx.x & (NCPY-1);
        atomicAdd(&d_bnaccM[layer][cp][lane],    S);
        atomicAdd(&d_bnaccM[layer][cp][64+lane], Q);
    }
}

// ---------------- fused coarse layer: block per dst ----------------
__global__ void k_fuseC(const __half* __restrict__ X1, const float* __restrict__ W,
                        __half* __restrict__ uout, const int* __restrict__ rs,
                        const uint2* __restrict__ eP, int layer, int ab1){
    __shared__ float Wsh[4*32*32];
    __shared__ float A1s[32], B1s[32];
    __shared__ float accS[8][4][32];
    __shared__ float sKS[8][4];
    __shared__ float Afin[4][32];
    int d = blockIdx.x, tid = threadIdx.x;
    int w = tid >> 5, lane = tid & 31;
    for (int idx = tid; idx < 4096; idx += 256) Wsh[idx] = W[idx];
    if (tid < 32){
        A1s[tid] = (ab1 >= 0) ? d_ssbL[ab1][tid]    : 1.f;
        B1s[tid] = (ab1 >= 0) ? d_ssbL[ab1][32+tid] : 0.f;
    }
    __syncthreads();
    int beg = rs[d], end = rs[d+1];
    float c0=0,c1=0,c2=0,c3=0, k0=0,k1=0,k2=0,k3=0;
    for (int p = beg + w; p < end; p += 8){
        uint2 e = eP[p];
        int s = (int)(e.x >> 14);
        float xv = __half2float(X1[(size_t)s*32 + lane]);
        float p0,p1,p2,p3;
        unpack_b(e, p0,p1,p2,p3);
        c0 += p0*xv; c1 += p1*xv; c2 += p2*xv; c3 += p3*xv;
        k0 += p0; k1 += p1; k2 += p2; k3 += p3;
    }
    accS[w][0][lane]=c0; accS[w][1][lane]=c1; accS[w][2][lane]=c2; accS[w][3][lane]=c3;
    if (lane == 0){ sKS[w][0]=k0; sKS[w][1]=k1; sKS[w][2]=k2; sKS[w][3]=k3; }
    __syncthreads();
    if (tid < 128){
        int k = tid >> 5, i = tid & 31;
        float a = 0.f, sk = 0.f;
        #pragma unroll
        for (int j = 0; j < 8; j++){ a += accS[j][k][i]; sk += sKS[j][k]; }
        Afin[k][i] = A1s[i]*a + B1s[i]*sk;
    }
    __syncthreads();
    if (w == 0){
        float v = 0.f;
        #pragma unroll
        for (int k = 0; k < 4; k++)
            for (int i = 0; i < 32; i++)
                v += Afin[k][i] * Wsh[(k*32+i)*32 + lane];
        int dg = end - beg; if (dg < 1) dg = 1;
        v /= (float)dg;
        v = (v > 0.f) ? v : expm1f(v);
        uout[(size_t)d*32 + lane] = __float2half(v);
        float ww = d_wv[d];
        int cp = blockIdx.x & (NCPY-1);
        atomicAdd(&d_bnaccM[layer][cp][lane],    ww*v);
        atomicAdd(&d_bnaccM[layer][cp][64+lane], ww*v*v);
    }
}

// ---------------- BN stats ----------------
__global__ void k_bnstats(const float* __restrict__ g, const float* __restrict__ b,
                          int layer, int cout, float denom, int useTw){
    __shared__ float part[2][128];
    __shared__ float tot[128];
    int t = threadIdx.x;        // 256
    int idx = t & 127, grp = t >> 7;
    float S = 0.f;
    for (int k = grp; k < NCPY; k += 2) S += d_bnaccM[layer][k][idx];
    part[grp][idx] = S;
    __syncthreads();
    if (t < 128) tot[t] = part[0][t] + part[1][t];
    __syncthreads();
    if (t < cout){
        float dn = useTw ? d_twD[0] : denom;
        float m = tot[t]/dn;
        float v = tot[64+t]/dn - m*m;
        float a = g[t]*rsqrtf(v + EPSn);
        d_ssbL[layer][t]    = a;
        d_ssbL[layer][32+t] = b[t] - m*a;
    }
}

// ---------------- pooling ----------------
__global__ void k_poolmax(const __half* __restrict__ u){
    int idx = blockIdx.x*blockDim.x + threadIdx.x;
    if (idx >= Nn*32) return;
    int n = idx >> 5, c = idx & 31;
    float v = __half2float(u[idx])*d_ssbL[5][c] + d_ssbL[5][32+c];
    atomicMax(&d_xpe[d_cid[n]*32 + c], encf(v));
}

__global__ void k_cellfin(){
    int idx = blockIdx.x*blockDim.x + threadIdx.x;
    if (idx >= Sn*32) return;
    int s = idx >> 5, c = idx & 31;
    int cnt = d_ccnt[s];
    if (c == 0){
        float inv = 1.f / (float)(cnt > 1 ? cnt : 1);
        d_pp[2*s]   *= inv;
        d_pp[2*s+1] *= inv;
        float w = (cnt > 0) ? 1.f : 0.f;
        d_wv[s] = w;
        if (cnt > 0) atomicAdd(&d_twD[0], 1.f);
    }
    d_xph[idx] = __float2half((cnt > 0) ? decf(d_xpe[idx]) : 0.f);
}

// coarse edge dedup with warp-aggregated counter + max
__global__ void k_cedges(const int* __restrict__ src, const int* __restrict__ dst){
    int e = blockIdx.x*blockDim.x + threadIdx.x;
    int cs = d_cid[src[e]], cd = d_cid[dst[e]];
    bool win = false;
    float m = 0.f;
    if (cs != cd){
        int b = cs / Gn;
        int key = b*Gn*Gn + (cs - b*Gn)*Gn + (cd - b*Gn);
        unsigned bit = 1u << (key & 31);
        unsigned old = atomicOr(&d_markb[key >> 5], bit);
        if (!(old & bit)){
            win = true;
            float cx = d_pp[2*cs]   - d_pp[2*cd];
            float cy = d_pp[2*cs+1] - d_pp[2*cd+1];
            m = fmaxf(fabsf(cx), fabsf(cy));
        }
    }
    unsigned wmask = __ballot_sync(0xFFFFFFFFu, win);
    float wm = m;
    #pragma unroll
    for (int o = 16; o; o >>= 1) wm = fmaxf(wm, __shfl_xor_sync(0xFFFFFFFFu, wm, o));
    int lane = threadIdx.x & 31;
    int nwin = __popc(wmask);
    int base = 0;
    if (lane == 0 && nwin){
        base = atomicAdd(&d_EcD[0], nwin);
        atomicMax(&d_mxD[0], __float_as_uint(wm));
    }
    base = __shfl_sync(0xFFFFFFFFu, base, 0);
    if (win){
        int i = base + __popc(wmask & ((1u << lane) - 1));
        d_csrc[i] = cs; d_cdst[i] = cd;
        atomicAdd(&d_degc[cd], 1);
    }
}

__global__ void k_scatterC(){
    int i = blockIdx.x*blockDim.x + threadIdx.x;
    if (i >= d_EcD[0]) return;
    int cs = d_csrc[i], cd = d_cdst[i];
    int p = atomicAdd(&d_curc[cd], 1);
    float mx = __uint_as_float(d_mxD[0]);
    float den = 2.f*mx + 1e-12f;
    float f0 = (d_pp[2*cs]   - d_pp[2*cd])   / den + 0.5f;
    float f1 = (d_pp[2*cs+1] - d_pp[2*cd+1]) / den + 0.5f;
    f0 = fminf(fmaxf(f0, 0.f), 1.f);
    f1 = fminf(fmaxf(f1, 0.f), 1.f);
    d_ePc[p] = pack_edge(cs, (1.f-f0)*(1.f-f1), f0*(1.f-f1), (1.f-f0)*f1);
}

// ---------------- final: per-batch weighted mean (with BN fold) + FC ----------------
__global__ void k_final(const __half* __restrict__ h, const float* __restrict__ fcW,
                        float* __restrict__ out){
    __shared__ float ss[8][33];
    __shared__ float sw8[8];
    __shared__ float gm[32];
    __shared__ float swv;
    int b = blockIdx.x;
    int lane = threadIdx.x & 31, w = threadIdx.x >> 5;
    float a7 = d_ssbL[7][lane], b7 = d_ssbL[7][32+lane];
    float acc = 0.f, accw = 0.f;
    for (int s = b*Gn + w; s < (b+1)*Gn; s += 8){
        float ww = d_wv[s];
        acc  += ww * (a7*__half2float(h[(size_t)s*32 + lane]) + b7);
        accw += ww;
    }
    ss[w][lane] = acc;
    if (lane == 0) sw8[w] = accw;
    __syncthreads();
    if (threadIdx.x < 32){
        float S = 0.f;
        #pragma unroll
        for (int j=0;j<8;j++) S += ss[j][threadIdx.x];
        gm[threadIdx.x] = S;
    }
    if (threadIdx.x == 0){
        float W = 0.f;
        #pragma unroll
        for (int j=0;j<8;j++) W += sw8[j];
        swv = W;
    }
    __syncthreads();
    if (threadIdx.x < 10){
        float o = 0.f;
        #pragma unroll
        for (int c=0;c<32;c++) o += (gm[c]/swv) * fcW[c*10 + threadIdx.x];
        out[b*10 + threadIdx.x] = o;
    }
}

// ---------------- host ----------------
template <typename T>
static T* devptr(const void* sym){
    void* p = nullptr;
    cudaGetSymbolAddress(&p, sym);
    return (T*)p;
}

extern "C" void kernel_launch(void* const* d_in, const int* in_sizes, int n_in,
                              void* d_out, int out_size){
    const float* x     = (const float*)d_in[0];
    const float* pos   = (const float*)d_in[1];
    const int*   batch = (const int*)  d_in[2];
    const int*   ei    = (const int*)  d_in[3];
    const int*   src   = ei;
    const int*   dst   = ei + Ee;
    const float* ea    = (const float*)d_in[4];
    const float* fcW   = (const float*)d_in[29];
    float* out = (float*)d_out;

    __half* pH0  = devptr<__half>(d_H0);
    __half* pHa  = devptr<__half>(d_Ha);
    __half* pHb  = devptr<__half>(d_Hb);
    __half* pHc  = devptr<__half>(d_Hc);
    __half* pxph = devptr<__half>(d_xph);
    __half* pCh0 = devptr<__half>(d_Ch0);
    __half* pCh1 = devptr<__half>(d_Ch1);
    int*    pdeg  = devptr<int>(d_deg);
    int*    prs   = devptr<int>(d_rs);
    int*    pcur  = devptr<int>(d_cur);
    uint2*  peP   = devptr<uint2>(d_eP);
    int*    pdegc = devptr<int>(d_degc);
    int*    prsc  = devptr<int>(d_rsc);
    int*    pcurc = devptr<int>(d_curc);
    uint2*  pePc  = devptr<uint2>(d_ePc);

    // prolog
    k_zeros<<<2048,256>>>();
    k_prep<<<Ee/256,256>>>(dst, pos, batch, x);
    k_scan1<<<256,1024>>>(pdeg, prs, Nn);
    k_scan2<<<1,256>>>(256);
    k_scan3<<<Nn/256,256>>>(pdeg, prs, pcur, Nn);
    k_scatter<<<Ee/256,256>>>(src, dst, ea);

    // fine layers (fused aggregate+GEMM+ELU+BNred); stats of layer l in ssbL[l]
    // blocks: each handles 8 warps * D dsts; D = 32/max(CIN,COUT)
    // l0: W1 (10->8), input H0 (stride 16, padded), D=2 -> Nn/16 blocks
    k_fuse<16,8><<<Nn/16,256>>>(pH0, nullptr, (const float*)d_in[5], pHa, prs, peP, 0, 10, -1, -1, Nn);
    k_bnstats<<<1,256>>>((const float*)d_in[6], (const float*)d_in[7], 0, 8, (float)Nn, 0);
    // l1: W2 (8->16), D=2
    k_fuse<8,16><<<Nn/16,256>>>(pHa, nullptr, (const float*)d_in[8], pHb, prs, peP, 1, 8, 0, -1, Nn);
    k_bnstats<<<1,256>>>((const float*)d_in[9], (const float*)d_in[10], 1, 16, (float)Nn, 0);
    // l2: W21 (16->16) -> Hc (residual source)
    k_fuse<16,16><<<Nn/16,256>>>(pHb, nullptr, (const float*)d_in[11], pHc, prs, peP, 2, 16, 1, -1, Nn);
    k_bnstats<<<1,256>>>((const float*)d_in[12], (const float*)d_in[13], 2, 16, (float)Nn, 0);
    // l3: W3 (16->16)
    k_fuse<16,16><<<Nn/16,256>>>(pHc, nullptr, (const float*)d_in[14], pHa, prs, peP, 3, 16, 2, -1, Nn);
    k_bnstats<<<1,256>>>((const float*)d_in[15], (const float*)d_in[16], 3, 16, (float)Nn, 0);
    // l4: W4 (16->16)
    k_fuse<16,16><<<Nn/16,256>>>(pHa, nullptr, (const float*)d_in[17], pHb, prs, peP, 4, 16, 3, -1, Nn);
    k_bnstats<<<1,256>>>((const float*)d_in[18], (const float*)d_in[19], 4, 16, (float)Nn, 0);
    // l5: W5 (16->32), residual: X1=Hb(fold4), X2=Hc(fold2), D=1 -> Nn/8 blocks
    k_fuse<16,32><<<Nn/8,256>>>(pHb, pHc, (const float*)d_in[20], pHa, prs, peP, 5, 16, 4, 2, Nn);
    k_bnstats<<<1,256>>>((const float*)d_in[21], (const float*)d_in[22], 5, 32, (float)Nn, 0);

    // pooling + coarse graph build (fold 5 applied in poolmax)
    k_poolmax<<<(Nn*32)/256,256>>>(pHa);
    k_cellfin<<<(Sn*32+255)/256,256>>>();
    k_cedges<<<Ee/256,256>>>(src, dst);
    k_scan1<<<(Sn+1023)/1024,1024>>>(pdegc, prsc, Sn);
    k_scan2<<<1,256>>>((Sn+1023)/1024);
    k_scan3<<<(Sn+255)/256,256>>>(pdegc, prsc, pcurc, Sn);
    k_scatterC<<<Ee/256,256>>>();

    // coarse layers (weighted BN)
    k_fuseC<<<Sn,256>>>(pxph, (const float*)d_in[23], pCh0, prsc, pePc, 6, -1);
    k_bnstats<<<1,256>>>((const float*)d_in[24], (const float*)d_in[25], 6, 32, 0.f, 1);
    k_fuseC<<<Sn,256>>>(pCh0, (const float*)d_in[26], pCh1, prsc, pePc, 7, 6);
    k_bnstats<<<1,256>>>((const float*)d_in[27], (const float*)d_in[28], 7, 32, 0.f, 1);

    k_final<<<Bn,256>>>(pCh1, fcW, out);
    (void)in_sizes; (void)n_in; (void)out_size;
}

// round 7
// speedup vs baseline: 1.0988x; 1.0988x over previous
#include <cuda_runtime.h>
#include <cuda_fp16.h>
#include <math.h>

#define Nn   262144
#define Ee   2097152
#define Bn   16
#define GXn  22
#define Gn   484
#define Sn   7744
#define EPSn 1e-5f
#define SXn  (16.0f/346.0f)
#define SYn  (12.0f/260.0f)
#define NCPY 64
#define MARKW ((Bn*Gn*Gn + 31)/32)

// ---------------- scratch ----------------
__device__ int      d_deg [Nn];
__device__ int      d_rs  [Nn+1];
__device__ int      d_cur [Nn+1];
__device__ uint2    d_eP  [Ee];
__device__ int      d_bsums[1024];
__device__ int      d_cid [Nn];
__device__ int      d_ccnt[Sn];
__device__ float    d_pp  [Sn*2];
__device__ unsigned d_xpe [Sn*32];
__device__ __half   d_xph [Sn*32];
__device__ float    d_wv  [Sn];
__device__ unsigned d_markb[MARKW];
__device__ int      d_EcD [1];
__device__ int      d_csrc[Ee];
__device__ int      d_cdst[Ee];
__device__ int      d_degc[Sn];
__device__ int      d_rsc [Sn+1];
__device__ int      d_curc[Sn+1];
__device__ uint2    d_ePc [Ee];
__device__ unsigned d_mxD [1];
__device__ float    d_twD [1];
__device__ __half   d_H0 [(size_t)Nn*16];
__device__ __half   d_Ha [(size_t)Nn*32];
__device__ __half   d_Hb [(size_t)Nn*32];
__device__ __half   d_Hc [(size_t)Nn*32];
__device__ __half   d_Ch0[Sn*32];
__device__ __half   d_Ch1[Sn*32];
__device__ float    d_bnaccM[8][NCPY][128];
__device__ float    d_ssbL[8][64];
__device__ int      d_tickS[2];
__device__ int      d_tickL[8];

// ---------------- helpers ----------------
__device__ __forceinline__ unsigned encf(float f){
    unsigned u = __float_as_uint(f);
    return (u & 0x80000000u) ? ~u : (u | 0x80000000u);
}
__device__ __forceinline__ float decf(unsigned u){
    return (u & 0x80000000u) ? __uint_as_float(u & 0x7FFFFFFFu) : __uint_as_float(~u);
}
__device__ __forceinline__ uint2 pack_edge(int s, float b0, float b1, float b2){
    unsigned q0 = (unsigned)__float2int_rn(b0*65535.f);
    unsigned q1 = (unsigned)__float2int_rn(b1*65535.f);
    unsigned q2 = (unsigned)__float2int_rn(b2*16383.f);
    uint2 r;
    r.x = ((unsigned)s << 14) | q2;
    r.y = q0 | (q1 << 16);
    return r;
}
__device__ __forceinline__ void unpack_b(uint2 e, float& b0, float& b1, float& b2, float& b3){
    b2 = (float)(e.x & 0x3FFFu) * (1.f/16383.f);
    b0 = (float)(e.y & 0xFFFFu) * (1.f/65535.f);
    b1 = (float)(e.y >> 16)     * (1.f/65535.f);
    b3 = 1.f - b0 - b1 - b2;
}

// ---------------- prolog ----------------
__global__ void k_zeros(){
    int i = blockIdx.x*blockDim.x + threadIdx.x;
    int st = gridDim.x*blockDim.x;
    for (int j=i; j<MARKW;    j+=st) d_markb[j]=0u;
    for (int j=i; j<Nn;       j+=st) d_deg[j]=0;
    for (int j=i; j<Sn;       j+=st){ d_ccnt[j]=0; d_degc[j]=0; }
    for (int j=i; j<Sn*2;     j+=st) d_pp[j]=0.f;
    for (int j=i; j<Sn*32;    j+=st) d_xpe[j]=0u;
    float* bm = &d_bnaccM[0][0][0];
    for (int j=i; j<8*NCPY*128; j+=st) bm[j]=0.f;
    if (i < 2) d_tickS[i]=0;
    if (i < 8) d_tickL[i]=0;
    if (i==0){ d_EcD[0]=0; d_mxD[0]=0u; d_twD[0]=0.f; }
}

__global__ void k_prep(const int* __restrict__ dst, const float* __restrict__ pos,
                       const int* __restrict__ batch, const float* __restrict__ x){
    int e = blockIdx.x*blockDim.x + threadIdx.x;
    if (e < Ee) atomicAdd(&d_deg[dst[e]], 1);
    if (e < Nn){
        float px = pos[2*(size_t)e], py = pos[2*(size_t)e+1];
        int cx = min(max((int)floorf(px / SXn), 0), GXn-1);
        int cy = min(max((int)floorf(py / SYn), 0), GXn-1);
        int cid = batch[e]*Gn + cy*GXn + cx;
        d_cid[e] = cid;
        atomicAdd(&d_ccnt[cid], 1);
        atomicAdd(&d_pp[2*cid],   px);
        atomicAdd(&d_pp[2*cid+1], py);
        const float* xr = x + (size_t)e*10;
        __half* hr = d_H0 + (size_t)e*16;
        #pragma unroll
        for (int i=0;i<10;i++) hr[i] = __float2half(xr[i]);
        #pragma unroll
        for (int i=10;i<16;i++) hr[i] = __float2half(0.f);
    }
}

// ---------------- scan: stage1+stage2 merged (last block scans block sums) ----
__global__ void k_scan12(const int* __restrict__ in, int* __restrict__ out, int n,
                         int* __restrict__ tick){
    __shared__ int sh[1024];
    __shared__ int isLast;
    int t = threadIdx.x;
    int base = blockIdx.x*1024;
    int v = (base+t < n) ? in[base+t] : 0;
    sh[t] = v; __syncthreads();
    for (int off=1; off<1024; off<<=1){
        int a = (t>=off) ? sh[t-off] : 0;
        __syncthreads();
        sh[t] += a;
        __syncthreads();
    }
    if (base+t < n) out[base+t] = sh[t]-v;
    if (t==1023) d_bsums[blockIdx.x] = sh[1023];
    __threadfence();
    if (t==0) isLast = (atomicAdd(tick,1) == (int)gridDim.x-1);
    __syncthreads();
    if (!isLast) return;
    int nb = gridDim.x;
    int bv = (t<nb) ? __ldcg(&d_bsums[t]) : 0;
    __syncthreads();
    sh[t] = bv; __syncthreads();
    for (int off=1; off<1024; off<<=1){
        int a = (t>=off) ? sh[t-off] : 0;
        __syncthreads();
        sh[t] += a;
        __syncthreads();
    }
    if (t<nb) d_bsums[t] = sh[t]-bv;
}
__global__ void k_scan3(const int* __restrict__ in, int* __restrict__ out,
                        int* __restrict__ cur, int n){
    int i = blockIdx.x*blockDim.x + threadIdx.x;
    if (i >= n) return;
    int v = out[i] + d_bsums[i>>10];
    out[i] = v; cur[i] = v;
    if (i == n-1){ int tot = v + in[i]; out[n]=tot; cur[n]=tot; }
}

__global__ void k_scatter(const int* __restrict__ src, const int* __restrict__ dst,
                          const float* __restrict__ ea){
    int e = blockIdx.x*blockDim.x + threadIdx.x;
    if (e >= Ee) return;
    float f0 = fminf(fmaxf(ea[2*(size_t)e  ], 0.f), 1.f);
    float f1 = fminf(fmaxf(ea[2*(size_t)e+1], 0.f), 1.f);
    int p = atomicAdd(&d_cur[dst[e]], 1);
    d_eP[p] = pack_edge(src[e], (1.f-f0)*(1.f-f1), f0*(1.f-f1), (1.f-f0)*f1);
}

// ---------- BN stats tail (shared by fuse kernels; run by last block) ----------
__device__ __forceinline__ void bn_stats_tail(const float* g, const float* b,
                                              int layer, int cout, float denom, int useTw){
    __shared__ float part[2][128];
    __shared__ float tot[128];
    int t = threadIdx.x;
    int idx = t & 127, grp = t >> 7;
    float S = 0.f;
    for (int k = grp; k < NCPY; k += 2) S += __ldcg(&d_bnaccM[layer][k][idx]);
    part[grp][idx] = S;
    __syncthreads();
    if (t < 128) tot[t] = part[0][t] + part[1][t];
    __syncthreads();
    if (t < cout){
        float dn = useTw ? __ldcg(&d_twD[0]) : denom;
        float m = tot[t]/dn;
        float v = tot[64+t]/dn - m*m;
        float a = g[t]*rsqrtf(v + EPSn);
        d_ssbL[layer][t]    = a;
        d_ssbL[layer][32+t] = b[t] - m*a;
    }
}

// ---------------- fused fine layer: aggregate -> GEMM -> ELU -> BN (+stats) ----
// D=4 dsts per warp; sub = 8 lanes; CPL = CINH/8 channels per lane.
template<int CINH, int COUT, bool RESID>
__global__ void k_fuse2(const __half* __restrict__ X1, const __half* __restrict__ X2,
                        const float* __restrict__ W, __half* __restrict__ uout,
                        const int* __restrict__ rs, const uint2* __restrict__ eP,
                        int layer, int wcin, int ab1, int ab2,
                        const float* __restrict__ g, const float* __restrict__ bb_){
    constexpr int CPL  = CINH/8;
    constexpr int NOUT = COUT/8;
    __shared__ float Wsh[4*CINH*COUT];
    __shared__ float A1s[32], B1s[32], A2s[32];
    __shared__ float As[8][4][4][CINH];
    __shared__ float sv[8][32][NOUT];
    __shared__ int   isLast;
    int tid = threadIdx.x;
    for (int idx = tid; idx < 4*wcin*COUT; idx += 256) Wsh[idx] = W[idx];
    if (tid < 32){
        A1s[tid] = (ab1 >= 0) ? d_ssbL[ab1][tid]    : 1.f;
        float b1 = (ab1 >= 0) ? d_ssbL[ab1][32+tid] : 0.f;
        A2s[tid] = (ab2 >= 0) ? d_ssbL[ab2][tid]    : 0.f;
        float b2 = (ab2 >= 0) ? d_ssbL[ab2][32+tid] : 0.f;
        B1s[tid] = b1 + b2;
    }
    __syncthreads();
    int w = tid >> 5, lane = tid & 31;
    int sub = lane >> 3, il = lane & 7;
    int d = (blockIdx.x*8 + w)*4 + sub;
    int beg = rs[d], end = rs[d+1];
    float c[4][CPL]; float er[4][CPL]; float kv[4];
    #pragma unroll
    for (int k=0;k<4;k++){ kv[k]=0.f;
        #pragma unroll
        for (int cc=0;cc<CPL;cc++){ c[k][cc]=0.f; er[k][cc]=0.f; } }
    const __half2* X1h = reinterpret_cast<const __half2*>(X1);
    const __half2* X2h = reinterpret_cast<const __half2*>(X2);
    int p = beg;
    for (; p + 1 < end; p += 2){
        uint2 ea = eP[p], eb = eP[p+1];
        int sa = (int)(ea.x >> 14), sb = (int)(eb.x >> 14);
        float p0,p1,p2,p3, q0,q1,q2,q3;
        unpack_b(ea,p0,p1,p2,p3);
        unpack_b(eb,q0,q1,q2,q3);
        kv[0]+=p0+q0; kv[1]+=p1+q1; kv[2]+=p2+q2; kv[3]+=p3+q3;
        if (CPL==2){
            float2 xa = __half22float2(X1h[(size_t)sa*8 + il]);
            float2 xb = __half22float2(X1h[(size_t)sb*8 + il]);
            c[0][0]+=p0*xa.x+q0*xb.x; c[0][1]+=p0*xa.y+q0*xb.y;
            c[1][0]+=p1*xa.x+q1*xb.x; c[1][1]+=p1*xa.y+q1*xb.y;
            c[2][0]+=p2*xa.x+q2*xb.x; c[2][1]+=p2*xa.y+q2*xb.y;
            c[3][0]+=p3*xa.x+q3*xb.x; c[3][1]+=p3*xa.y+q3*xb.y;
            if (RESID){
                float2 ya = __half22float2(X2h[(size_t)sa*8 + il]);
                float2 yb = __half22float2(X2h[(size_t)sb*8 + il]);
                er[0][0]+=p0*ya.x+q0*yb.x; er[0][1]+=p0*ya.y+q0*yb.y;
                er[1][0]+=p1*ya.x+q1*yb.x; er[1][1]+=p1*ya.y+q1*yb.y;
                er[2][0]+=p2*ya.x+q2*yb.x; er[2][1]+=p2*ya.y+q2*yb.y;
                er[3][0]+=p3*ya.x+q3*yb.x; er[3][1]+=p3*ya.y+q3*yb.y;
            }
        } else {
            float xa = __half2float(X1[(size_t)sa*8 + il]);
            float xb = __half2float(X1[(size_t)sb*8 + il]);
            c[0][0]+=p0*xa+q0*xb; c[1][0]+=p1*xa+q1*xb;
            c[2][0]+=p2*xa+q2*xb; c[3][0]+=p3*xa+q3*xb;
        }
    }
    if (p < end){
        uint2 ea = eP[p];
        int sa = (int)(ea.x >> 14);
        float p0,p1,p2,p3;
        unpack_b(ea,p0,p1,p2,p3);
        kv[0]+=p0; kv[1]+=p1; kv[2]+=p2; kv[3]+=p3;
        if (CPL==2){
            float2 xa = __half22float2(X1h[(size_t)sa*8 + il]);
            c[0][0]+=p0*xa.x; c[0][1]+=p0*xa.y;
            c[1][0]+=p1*xa.x; c[1][1]+=p1*xa.y;
            c[2][0]+=p2*xa.x; c[2][1]+=p2*xa.y;
            c[3][0]+=p3*xa.x; c[3][1]+=p3*xa.y;
            if (RESID){
                float2 ya = __half22float2(X2h[(size_t)sa*8 + il]);
                er[0][0]+=p0*ya.x; er[0][1]+=p0*ya.y;
                er[1][0]+=p1*ya.x; er[1][1]+=p1*ya.y;
                er[2][0]+=p2*ya.x; er[2][1]+=p2*ya.y;
                er[3][0]+=p3*ya.x; er[3][1]+=p3*ya.y;
            }
        } else {
            float xa = __half2float(X1[(size_t)sa*8 + il]);
            c[0][0]+=p0*xa; c[1][0]+=p1*xa; c[2][0]+=p2*xa; c[3][0]+=p3*xa;
        }
    }
    // stage with BN fold
    #pragma unroll
    for (int k=0;k<4;k++){
        #pragma unroll
        for (int cc=0;cc<CPL;cc++){
            int ch = il*CPL + cc;
            float a = A1s[ch]*c[k][cc] + B1s[ch]*kv[k];
            if (RESID) a += A2s[ch]*er[k][cc];
            As[w][sub][k][ch] = a;
        }
    }
    __syncwarp();
    // GEMM: lane -> dst sub, channels (lane&7)+8q
    int dg = end - beg; if (dg < 1) dg = 1;
    float inv = 1.f / (float)dg;
    #pragma unroll
    for (int q=0;q<NOUT;q++){
        int ch = (lane & 7) + 8*q;
        float v = 0.f;
        for (int k=0;k<4;k++){
            const float* ak = &As[w][sub][k][0];
            const float* wk = &Wsh[k*wcin*COUT + ch];
            for (int i=0;i<wcin;i++) v += ak[i] * wk[i*COUT];
        }
        v *= inv;
        v = (v > 0.f) ? v : expm1f(v);
        uout[(size_t)d*COUT + ch] = __float2half(v);
        sv[w][lane][q] = v;
    }
    __syncthreads();
    if (w == 0 && lane < COUT){
        float S = 0.f, Q = 0.f;
        int cl = lane & 7, q = lane >> 3;
        #pragma unroll
        for (int j=0;j<8;j++){
            #pragma unroll
            for (int s2=0;s2<4;s2++){
                float v = sv[j][s2*8 + cl][q];
                S += v; Q += v*v;
            }
        }
        int cp = blockIdx.x & (NCPY-1);
        atomicAdd(&d_bnaccM[layer][cp][lane],    S);
        atomicAdd(&d_bnaccM[layer][cp][64+lane], Q);
    }
    __threadfence();
    __syncthreads();
    if (tid == 0) isLast = (atomicAdd(&d_tickL[layer],1) == (int)gridDim.x-1);
    __syncthreads();
    if (isLast) bn_stats_tail(g, bb_, layer, COUT, (float)Nn, 0);
}

// ---------------- fused coarse layer: block per dst ----------------
__global__ void k_fuseC(const __half* __restrict__ X1, const float* __restrict__ W,
                        __half* __restrict__ uout, const int* __restrict__ rs,
                        const uint2* __restrict__ eP, int layer, int ab1,
                        const float* __restrict__ g, const float* __restrict__ bb_){
    __shared__ float Wsh[4*32*32];
    __shared__ float A1s[32], B1s[32];
    __shared__ float accS[8][4][32];
    __shared__ float sKS[8][4];
    __shared__ float Afin[4][32];
    __shared__ int   isLast;
    int d = blockIdx.x, tid = threadIdx.x;
    int w = tid >> 5, lane = tid & 31;
    for (int idx = tid; idx < 4096; idx += 256) Wsh[idx] = W[idx];
    if (tid < 32){
        A1s[tid] = (ab1 >= 0) ? d_ssbL[ab1][tid]    : 1.f;
        B1s[tid] = (ab1 >= 0) ? d_ssbL[ab1][32+tid] : 0.f;
    }
    __syncthreads();
    int beg = rs[d], end = rs[d+1];
    float c0=0,c1=0,c2=0,c3=0, k0=0,k1=0,k2=0,k3=0;
    for (int p = beg + w; p < end; p += 8){
        uint2 e = eP[p];
        int s = (int)(e.x >> 14);
        float xv = __half2float(X1[(size_t)s*32 + lane]);
        float p0,p1,p2,p3;
        unpack_b(e, p0,p1,p2,p3);
        c0 += p0*xv; c1 += p1*xv; c2 += p2*xv; c3 += p3*xv;
        k0 += p0; k1 += p1; k2 += p2; k3 += p3;
    }
    accS[w][0][lane]=c0; accS[w][1][lane]=c1; accS[w][2][lane]=c2; accS[w][3][lane]=c3;
    if (lane == 0){ sKS[w][0]=k0; sKS[w][1]=k1; sKS[w][2]=k2; sKS[w][3]=k3; }
    __syncthreads();
    if (tid < 128){
        int k = tid >> 5, i = tid & 31;
        float a = 0.f, sk = 0.f;
        #pragma unroll
        for (int j = 0; j < 8; j++){ a += accS[j][k][i]; sk += sKS[j][k]; }
        Afin[k][i] = A1s[i]*a + B1s[i]*sk;
    }
    __syncthreads();
    if (w == 0){
        float v = 0.f;
        #pragma unroll
        for (int k = 0; k < 4; k++)
            for (int i = 0; i < 32; i++)
                v += Afin[k][i] * Wsh[(k*32+i)*32 + lane];
        int dg = end - beg; if (dg < 1) dg = 1;
        v /= (float)dg;
        v = (v > 0.f) ? v : expm1f(v);
        uout[(size_t)d*32 + lane] = __float2half(v);
        float ww = d_wv[d];
        int cp = blockIdx.x & (NCPY-1);
        atomicAdd(&d_bnaccM[layer][cp][lane],    ww*v);
        atomicAdd(&d_bnaccM[layer][cp][64+lane], ww*v*v);
    }
    __threadfence();
    __syncthreads();
    if (tid == 0) isLast = (atomicAdd(&d_tickL[layer],1) == (int)gridDim.x-1);
    __syncthreads();
    if (isLast) bn_stats_tail(g, bb_, layer, 32, 0.f, 1);
}

// ---------------- pooling ----------------
__global__ void k_poolmax(const __half* __restrict__ u){
    int idx = blockIdx.x*blockDim.x + threadIdx.x;
    if (idx >= Nn*32) return;
    int n = idx >> 5, c = idx & 31;
    float v = __half2float(u[idx])*d_ssbL[5][c] + d_ssbL[5][32+c];
    atomicMax(&d_xpe[d_cid[n]*32 + c], encf(v));
}

__global__ void k_cellfin(){
    int idx = blockIdx.x*blockDim.x + threadIdx.x;
    if (idx >= Sn*32) return;
    int s = idx >> 5, c = idx & 31;
    int cnt = d_ccnt[s];
    if (c == 0){
        float inv = 1.f / (float)(cnt > 1 ? cnt : 1);
        d_pp[2*s]   *= inv;
        d_pp[2*s+1] *= inv;
        float w = (cnt > 0) ? 1.f : 0.f;
        d_wv[s] = w;
        if (cnt > 0) atomicAdd(&d_twD[0], 1.f);
    }
    d_xph[idx] = __float2half((cnt > 0) ? decf(d_xpe[idx]) : 0.f);
}

__global__ void k_cedges(const int* __restrict__ src, const int* __restrict__ dst){
    int e = blockIdx.x*blockDim.x + threadIdx.x;
    int cs = d_cid[src[e]], cd = d_cid[dst[e]];
    bool win = false;
    float m = 0.f;
    if (cs != cd){
        int b = cs / Gn;
        int key = b*Gn*Gn + (cs - b*Gn)*Gn + (cd - b*Gn);
        unsigned bit = 1u << (key & 31);
        unsigned old = atomicOr(&d_markb[key >> 5], bit);
        if (!(old & bit)){
            win = true;
            float cx = d_pp[2*cs]   - d_pp[2*cd];
            float cy = d_pp[2*cs+1] - d_pp[2*cd+1];
            m = fmaxf(fabsf(cx), fabsf(cy));
        }
    }
    unsigned wmask = __ballot_sync(0xFFFFFFFFu, win);
    float wm = m;
    #pragma unroll
    for (int o = 16; o; o >>= 1) wm = fmaxf(wm, __shfl_xor_sync(0xFFFFFFFFu, wm, o));
    int lane = threadIdx.x & 31;
    int nwin = __popc(wmask);
    int base = 0;
    if (lane == 0 && nwin){
        base = atomicAdd(&d_EcD[0], nwin);
        atomicMax(&d_mxD[0], __float_as_uint(wm));
    }
    base = __shfl_sync(0xFFFFFFFFu, base, 0);
    if (win){
        int i = base + __popc(wmask & ((1u << lane) - 1));
        d_csrc[i] = cs; d_cdst[i] = cd;
        atomicAdd(&d_degc[cd], 1);
    }
}

__global__ void k_scatterC(){
    int i = blockIdx.x*blockDim.x + threadIdx.x;
    if (i >= d_EcD[0]) return;
    int cs = d_csrc[i], cd = d_cdst[i];
    int p = atomicAdd(&d_curc[cd], 1);
    float mx = __uint_as_float(d_mxD[0]);
    float den = 2.f*mx + 1e-12f;
    float f0 = (d_pp[2*cs]   - d_pp[2*cd])   / den + 0.5f;
    float f1 = (d_pp[2*cs+1] - d_pp[2*cd+1]) / den + 0.5f;
    f0 = fminf(fmaxf(f0, 0.f), 1.f);
    f1 = fminf(fmaxf(f1, 0.f), 1.f);
    d_ePc[p] = pack_edge(cs, (1.f-f0)*(1.f-f1), f0*(1.f-f1), (1.f-f0)*f1);
}

// ---------------- final ----------------
__global__ void k_final(const __half* __restrict__ h, const float* __restrict__ fcW,
                        float* __restrict__ out){
    __shared__ float ss[8][33];
    __shared__ float sw8[8];
    __shared__ float gm[32];
    __shared__ float swv;
    int b = blockIdx.x;
    int lane = threadIdx.x & 31, w = threadIdx.x >> 5;
    float a7 = d_ssbL[7][lane], b7 = d_ssbL[7][32+lane];
    float acc = 0.f, accw = 0.f;
    for (int s = b*Gn + w; s < (b+1)*Gn; s += 8){
        float ww = d_wv[s];
        acc  += ww * (a7*__half2float(h[(size_t)s*32 + lane]) + b7);
        accw += ww;
    }
    ss[w][lane] = acc;
    if (lane == 0) sw8[w] = accw;
    __syncthreads();
    if (threadIdx.x < 32){
        float S = 0.f;
        #pragma unroll
        for (int j=0;j<8;j++) S += ss[j][threadIdx.x];
        gm[threadIdx.x] = S;
    }
    if (threadIdx.x == 0){
        float W = 0.f;
        #pragma unroll
        for (int j=0;j<8;j++) W += sw8[j];
        swv = W;
    }
    __syncthreads();
    if (threadIdx.x < 10){
        float o = 0.f;
        #pragma unroll
        for (int c=0;c<32;c++) o += (gm[c]/swv) * fcW[c*10 + threadIdx.x];
        out[b*10 + threadIdx.x] = o;
    }
}

// ---------------- host ----------------
template <typename T>
static T* devptr(const void* sym){
    void* p = nullptr;
    cudaGetSymbolAddress(&p, sym);
    return (T*)p;
}

extern "C" void kernel_launch(void* const* d_in, const int* in_sizes, int n_in,
                              void* d_out, int out_size){
    const float* x     = (const float*)d_in[0];
    const float* pos   = (const float*)d_in[1];
    const int*   batch = (const int*)  d_in[2];
    const int*   ei    = (const int*)  d_in[3];
    const int*   src   = ei;
    const int*   dst   = ei + Ee;
    const float* ea    = (const float*)d_in[4];
    const float* fcW   = (const float*)d_in[29];
    float* out = (float*)d_out;

    __half* pH0  = devptr<__half>(d_H0);
    __half* pHa  = devptr<__half>(d_Ha);
    __half* pHb  = devptr<__half>(d_Hb);
    __half* pHc  = devptr<__half>(d_Hc);
    __half* pxph = devptr<__half>(d_xph);
    __half* pCh0 = devptr<__half>(d_Ch0);
    __half* pCh1 = devptr<__half>(d_Ch1);
    int*    pdeg  = devptr<int>(d_deg);
    int*    prs   = devptr<int>(d_rs);
    int*    pcur  = devptr<int>(d_cur);
    uint2*  peP   = devptr<uint2>(d_eP);
    int*    pdegc = devptr<int>(d_degc);
    int*    prsc  = devptr<int>(d_rsc);
    int*    pcurc = devptr<int>(d_curc);
    uint2*  pePc  = devptr<uint2>(d_ePc);
    int*    ptick = devptr<int>(d_tickS);

    // prolog: 5 launches before first fuse -> launch #5 is k_fuse2<16,8> (ncu target)
    k_zeros<<<2048,256>>>();
    k_prep<<<Ee/256,256>>>(dst, pos, batch, x);
    k_scan12<<<256,1024>>>(pdeg, prs, Nn, ptick);
    k_scan3<<<Nn/256,256>>>(pdeg, prs, pcur, Nn);
    k_scatter<<<Ee/256,256>>>(src, dst, ea);

    // fine layers, fused BN stats (last-block); grid = Nn/32 (D=4, 8 warps)
    k_fuse2<16, 8,false><<<Nn/32,256>>>(pH0, nullptr, (const float*)d_in[5],  pHa, prs, peP, 0, 10, -1, -1, (const float*)d_in[6],  (const float*)d_in[7]);
    k_fuse2< 8,16,false><<<Nn/32,256>>>(pHa, nullptr, (const float*)d_in[8],  pHb, prs, peP, 1,  8,  0, -1, (const float*)d_in[9],  (const float*)d_in[10]);
    k_fuse2<16,16,false><<<Nn/32,256>>>(pHb, nullptr, (const float*)d_in[11], pHc, prs, peP, 2, 16,  1, -1, (const float*)d_in[12], (const float*)d_in[13]);
    k_fuse2<16,16,false><<<Nn/32,256>>>(pHc, nullptr, (const float*)d_in[14], pHa, prs, peP, 3, 16,  2, -1, (const float*)d_in[15], (const float*)d_in[16]);
    k_fuse2<16,16,false><<<Nn/32,256>>>(pHa, nullptr, (const float*)d_in[17], pHb, prs, peP, 4, 16,  3, -1, (const float*)d_in[18], (const float*)d_in[19]);
    k_fuse2<16,32,true ><<<Nn/32,256>>>(pHb, pHc,     (const float*)d_in[20], pHa, prs, peP, 5, 16,  4,  2, (const float*)d_in[21], (const float*)d_in[22]);

    // pooling + coarse graph build
    k_poolmax<<<(Nn*32)/256,256>>>(pHa);
    k_cellfin<<<(Sn*32+255)/256,256>>>();
    k_cedges<<<Ee/256,256>>>(src, dst);
    k_scan12<<<8,1024>>>(pdegc, prsc, Sn, ptick+1);
    k_scan3<<<(Sn+255)/256,256>>>(pdegc, prsc, pcurc, Sn);
    k_scatterC<<<Ee/256,256>>>();

    // coarse layers (weighted BN, fused stats)
    k_fuseC<<<Sn,256>>>(pxph, (const float*)d_in[23], pCh0, prsc, pePc, 6, -1, (const float*)d_in[24], (const float*)d_in[25]);
    k_fuseC<<<Sn,256>>>(pCh0, (const float*)d_in[26], pCh1, prsc, pePc, 7,  6, (const float*)d_in[27], (const float*)d_in[28]);

    k_final<<<Bn,256>>>(pCh1, fcW, out);
    (void)in_sizes; (void)n_in; (void)out_size;
}